// round 14
// baseline (speedup 1.0000x reference)
#include <cuda_runtime.h>
#include <math.h>

#define B_      256
#define T_      512
#define N_      512
#define DK_     64
#define DV_     256
#define S_      64
#define F_      64
#define SLICES_ 4
#define RPS_    128   // memory rows per slice
#define TAU     1e-8f // w threshold: dropped mass <= ~512*TAU per step

// -------- device scratch (static __device__ arrays; no allocations) --------
__device__ float  g_keyT[DK_ * N_];                  // key_memory transposed (DK, N)
__device__ float2 g_wlist[(N_ + 1) * SLICES_ * RPS_]; // compacted (w, row) per (c, slice)
__device__ int    g_wcnt[(N_ + 1) * SLICES_];         // active count per (c, slice)
__device__ float  g_etab[(2 * N_ + 1) * DV_];         // sigmoid(We v + be) per interaction id
__device__ float  g_atab[(2 * N_ + 1) * DV_];         // tanh(Wa v + ba)   per interaction id
__device__ float  g_qc[(N_ + 1) * S_];                // W1[:,DV:] @ q + b1 per concept id
__device__ float  g_rpart[134217728];                 // (B, T, SLICES, DV) partial reads

// ---------------------------------------------------------------------------
// Precompute 0: transpose key_memory (N, DK) -> (DK, N)
__global__ void k_transpose(const float* __restrict__ key) {
    int idx = blockIdx.x * blockDim.x + threadIdx.x;   // 0 .. N*DK-1
    int n = idx >> 6;
    int k = idx & 63;
    g_keyT[k * N_ + n] = key[idx];
}

// Precompute 1: softmax attention per concept, compacted to active (w, row)
// lists per slice with a deterministic ballot/scan (index-ascending order).
__global__ void k_wtab(const float* __restrict__ cemb) {
    int c = blockIdx.x;        // 0..512
    int n = threadIdx.x;       // 0..511
    __shared__ float q[DK_];
    __shared__ float red[512];
    __shared__ int wcnts[16];
    if (n < DK_) q[n] = cemb[c * DK_ + n];
    __syncthreads();
    float acc = 0.f;
#pragma unroll
    for (int k = 0; k < DK_; k++) acc = fmaf(q[k], g_keyT[k * N_ + n], acc);
    red[n] = acc; __syncthreads();
    for (int s = 256; s > 0; s >>= 1) { if (n < s) red[n] = fmaxf(red[n], red[n + s]); __syncthreads(); }
    float mx = red[0]; __syncthreads();
    float e = expf(acc - mx);
    red[n] = e; __syncthreads();
    for (int s = 256; s > 0; s >>= 1) { if (n < s) red[n] += red[n + s]; __syncthreads(); }
    float w = e / red[0];

    // deterministic compaction: each warp lies wholly inside one slice (128 = 4 warps)
    bool pred = (w >= TAU);
    unsigned mask = __ballot_sync(0xffffffffu, pred);
    int lane = n & 31, warp = n >> 5, slice = n >> 7, win = warp & 3;
    if (lane == 0) wcnts[warp] = __popc(mask);
    __syncthreads();
    int base = 0;
#pragma unroll
    for (int k = 0; k < 3; k++) if (k < win) base += wcnts[(slice << 2) + k];
    if (pred) {
        int pos = base + __popc(mask & ((1u << lane) - 1u));
        g_wlist[(c * SLICES_ + slice) * RPS_ + pos] = make_float2(w, __int_as_float(n & 127));
    }
    if ((n & 127) == 0)
        g_wcnt[c * SLICES_ + slice] = wcnts[slice * 4] + wcnts[slice * 4 + 1]
                                    + wcnts[slice * 4 + 2] + wcnts[slice * 4 + 3];
}

// Precompute 2: erase/add tables per interaction id (GEMV batched over 16 ids/block)
#define IPB 16
__global__ void k_eatab(const float* __restrict__ iemb,
                        const float* __restrict__ We, const float* __restrict__ be,
                        const float* __restrict__ Wa, const float* __restrict__ ba) {
    int i0 = blockIdx.x * IPB;
    int d = threadIdx.x;                 // 0..255 output dim
    __shared__ float v[IPB][DV_];
    for (int x = threadIdx.x; x < IPB * DV_; x += blockDim.x) {
        int ii = x >> 8, k = x & 255;
        int gi = i0 + ii;
        v[ii][k] = (gi <= 2 * N_) ? iemb[gi * DV_ + k] : 0.f;
    }
    __syncthreads();
    float aE[IPB], aA[IPB];
#pragma unroll
    for (int ii = 0; ii < IPB; ii++) { aE[ii] = 0.f; aA[ii] = 0.f; }
    for (int k = 0; k < DV_; k++) {
        float we = We[d * DV_ + k];
        float wa = Wa[d * DV_ + k];
#pragma unroll
        for (int ii = 0; ii < IPB; ii++) {
            aE[ii] = fmaf(we, v[ii][k], aE[ii]);
            aA[ii] = fmaf(wa, v[ii][k], aA[ii]);
        }
    }
    float beV = be[d], baV = ba[d];
#pragma unroll
    for (int ii = 0; ii < IPB; ii++) {
        int gi = i0 + ii;
        if (gi <= 2 * N_) {
            g_etab[gi * DV_ + d] = 1.f / (1.f + expf(-(aE[ii] + beV)));
            g_atab[gi * DV_ + d] = tanhf(aA[ii] + baV);
        }
    }
}

// Precompute 3: qc[c][s] = b1[s] + sum_k W1[s][DV+k] * q_c[k]
__global__ void k_qc(const float* __restrict__ cemb, const float* __restrict__ W1,
                     const float* __restrict__ b1) {
    int c = blockIdx.x;
    int s = threadIdx.x;     // 0..63
    __shared__ float q[DK_];
    if (s < DK_) q[s] = cemb[c * DK_ + s];
    __syncthreads();
    float acc = b1[s];
#pragma unroll
    for (int k = 0; k < DK_; k++) acc = fmaf(W1[s * (DV_ + DK_) + DV_ + k], q[k], acc);
    g_qc[c * S_ + s] = acc;
}

// ---------------------------------------------------------------------------
// Main recurrence (SPARSE): one CTA per (batch, slice). Slice state
// (128 rows x 256 cols fp32 = 128KB) lives in SMEM. Per step, only rows with
// w >= TAU are read/updated (softmax is highly peaked: ~10-15% active).
// 512 threads: col = t&255, half = t>>8; the two halves split active rows.
// Per active row per column: r += w*m ; u = fma(-e, m, a) ; m = fma(w, u, m).
// cnt / (-e) / a are register-carried with a 1-step prefetch; only the
// (w,row) list is staged through SMEM (double-buffered).
#define SMEM_MAIN (131072 + 2048 + 2048 + 4096)
__global__ void __launch_bounds__(512, 1)
k_main(const int* __restrict__ concepts, const int* __restrict__ interactions,
       const float* __restrict__ vmem) {
    extern __shared__ char smraw[];
    float*  m_s   = (float*)smraw;                         // 32768 floats
    float2* swl   = (float2*)(smraw + 131072);             // [2][128] (w, row)
    float*  rex   = (float*)(smraw + 131072 + 2048);       // 512 partials
    int*    c_seq = (int*)(smraw + 131072 + 2048 + 2048);  // 512
    int*    i_seq = c_seq + 512;                           // 512

    int batch = blockIdx.x >> 2;
    int slice = blockIdx.x & 3;
    int t = threadIdx.x;
    int col = t & 255, half = t >> 8;

    c_seq[t] = concepts[batch * T_ + t];
    i_seq[t] = interactions[batch * T_ + t];

    // load slice of value memory (contiguous rows) into SMEM
    {
        const float4* src = (const float4*)(vmem + (size_t)slice * RPS_ * DV_);
        float4* dst = (float4*)m_s;
#pragma unroll
        for (int i = 0; i < 16; i++) dst[t + i * 512] = src[t + i * 512];
    }
    __syncthreads();

    // prologue: stage step 0
    int cnt; float ne, aa;
    {
        int c0 = c_seq[0], i0 = i_seq[0];
        int ls = c0 * SLICES_ + slice;
        cnt = g_wcnt[ls];
        if (t < 128) swl[t] = g_wlist[ls * RPS_ + t];
        ne = -g_etab[i0 * DV_ + col];
        aa =  g_atab[i0 * DV_ + col];
    }
    __syncthreads();

    size_t obase = (size_t)batch * T_ * (SLICES_ * DV_) + (size_t)slice * DV_;

    for (int step = 0; step < T_; step++) {
        int cur = step & 1;
        // prefetch next step's list + gates into registers
        float2 pl = make_float2(0.f, 0.f);
        int pcnt = 0; float pe = 0.f, pa = 0.f;
        if (step + 1 < T_) {
            int cn = c_seq[step + 1], in2 = i_seq[step + 1];
            int ls = cn * SLICES_ + slice;
            pcnt = g_wcnt[ls];
            if (t < 128) pl = g_wlist[ls * RPS_ + t];
            pe = -g_etab[in2 * DV_ + col];
            pa =  g_atab[in2 * DV_ + col];
        }

        // sparse read + erase-add update over active rows
        const float2* wl = swl + (cur ? 128 : 0);
        float r = 0.f;
        for (int j = half; j < cnt; j += 2) {
            float2 e2 = wl[j];                     // uniform broadcast
            float wv = e2.x;
            int row = __float_as_int(e2.y);
            float* mp = m_s + (row << 8) + col;
            float mv = *mp;
            r = fmaf(wv, mv, r);
            float u = fmaf(ne, mv, aa);
            *mp = fmaf(wv, u, mv);
        }
        rex[t] = r;
        if (step + 1 < T_ && t < 128) swl[(cur ? 0 : 128) + t] = pl;
        __syncthreads();
        if (t < 256)
            g_rpart[obase + (size_t)step * (SLICES_ * DV_) + t] = rex[t] + rex[t + 256];
        __syncthreads();
        cnt = pcnt; ne = pe; aa = pa;
    }
}

// ---------------------------------------------------------------------------
// Prediction head: reduce slice partials of r, then 320->64->64->1 MLP.
__global__ void k_mlp(const int* __restrict__ concepts,
                      const float* __restrict__ W1, const float* __restrict__ W2,
                      const float* __restrict__ b2, const float* __restrict__ W3,
                      const float* __restrict__ b3, float* __restrict__ out) {
    extern __shared__ float sm[];
    float* W1s = sm;                  // 64*260 = 16640
    float* W2s = W1s + 64 * 260;      // 64*68  = 4352
    float* W3s = W2s + 64 * 68;       // 64
    float* b2s = W3s + 64;            // 64
    float* rsm = b2s + 64;            // 16*256 = 4096
    float* h1s = rsm + 16 * 256;      // 16*64  = 1024   (total 26240 floats)
    int tid = threadIdx.x;
    for (int x = tid; x < 64 * 256; x += 256) {
        int s = x >> 8, d = x & 255;
        W1s[s * 260 + d] = W1[s * 320 + d];       // first DV columns of W1
    }
    for (int x = tid; x < 64 * 64; x += 256) {
        int s = x >> 6, k = x & 63;
        W2s[s * 68 + k] = W2[s * 64 + k];
    }
    if (tid < 64) { W3s[tid] = W3[tid]; b2s[tid] = b2[tid]; }
    __syncthreads();

    int w = tid >> 5, lane = tid & 31;
    float b3v = b3[0];
    float4* rA4 = (float4*)(rsm + (w * 2 + 0) * 256);
    float4* rB4 = (float4*)(rsm + (w * 2 + 1) * 256);
    float* h1A = h1s + (w * 2) * 64;
    float* h1B = h1A + 64;
    int pair0 = blockIdx.x * 8 + w;   // 2048 warp-slots, 65536 pairs, 32 iters

    for (int it = 0; it < 32; it++) {
        int pair = pair0 + it * 2048;
        int itemA = pair * 2, itemB = itemA + 1;
        const float4* rpA = (const float4*)(g_rpart + (size_t)itemA * (SLICES_ * DV_));
        const float4* rpB = (const float4*)(g_rpart + (size_t)itemB * (SLICES_ * DV_));
#pragma unroll
        for (int jj = 0; jj < 2; jj++) {
            int p = lane + 32 * jj;   // float4 index 0..63
            float4 a0 = rpA[p], a1 = rpA[64 + p], a2 = rpA[128 + p], a3 = rpA[192 + p];
            rA4[p] = make_float4(a0.x + a1.x + a2.x + a3.x, a0.y + a1.y + a2.y + a3.y,
                                 a0.z + a1.z + a2.z + a3.z, a0.w + a1.w + a2.w + a3.w);
            float4 c0 = rpB[p], c1 = rpB[64 + p], c2 = rpB[128 + p], c3 = rpB[192 + p];
            rB4[p] = make_float4(c0.x + c1.x + c2.x + c3.x, c0.y + c1.y + c2.y + c3.y,
                                 c0.z + c1.z + c2.z + c3.z, c0.w + c1.w + c2.w + c3.w);
        }
        __syncwarp();
        int cA = concepts[itemA];
        int cB = concepts[itemB];
        float acc00 = g_qc[cA * 64 + lane];
        float acc01 = g_qc[cA * 64 + lane + 32];
        float acc10 = g_qc[cB * 64 + lane];
        float acc11 = g_qc[cB * 64 + lane + 32];
#pragma unroll 8
        for (int d4 = 0; d4 < 64; d4++) {
            float4 ra = rA4[d4];
            float4 rb = rB4[d4];
            float4 w0 = *(const float4*)&W1s[lane * 260 + d4 * 4];
            float4 w1 = *(const float4*)&W1s[(lane + 32) * 260 + d4 * 4];
            acc00 += w0.x * ra.x + w0.y * ra.y + w0.z * ra.z + w0.w * ra.w;
            acc10 += w0.x * rb.x + w0.y * rb.y + w0.z * rb.z + w0.w * rb.w;
            acc01 += w1.x * ra.x + w1.y * ra.y + w1.z * ra.z + w1.w * ra.w;
            acc11 += w1.x * rb.x + w1.y * rb.y + w1.z * rb.z + w1.w * rb.w;
        }
        h1A[lane]      = fmaxf(acc00, 0.f);
        h1A[lane + 32] = fmaxf(acc01, 0.f);
        h1B[lane]      = fmaxf(acc10, 0.f);
        h1B[lane + 32] = fmaxf(acc11, 0.f);
        __syncwarp();
        float h2[2][2];
#pragma unroll
        for (int o = 0; o < 2; o++) {
            int s = lane + 32 * o;
            float aA = b2s[s], aB = aA;
#pragma unroll
            for (int k4 = 0; k4 < 16; k4++) {
                float4 wv = *(const float4*)&W2s[s * 68 + k4 * 4];
                float4 ha = *(const float4*)&h1A[k4 * 4];
                float4 hb = *(const float4*)&h1B[k4 * 4];
                aA += wv.x * ha.x + wv.y * ha.y + wv.z * ha.z + wv.w * ha.w;
                aB += wv.x * hb.x + wv.y * hb.y + wv.z * hb.z + wv.w * hb.w;
            }
            h2[0][o] = fmaxf(aA, 0.f);
            h2[1][o] = fmaxf(aB, 0.f);
        }
        float pA = W3s[lane] * h2[0][0] + W3s[lane + 32] * h2[0][1];
        float pB = W3s[lane] * h2[1][0] + W3s[lane + 32] * h2[1][1];
#pragma unroll
        for (int off = 16; off > 0; off >>= 1) {
            pA += __shfl_xor_sync(0xffffffffu, pA, off);
            pB += __shfl_xor_sync(0xffffffffu, pB, off);
        }
        if (lane == 0) {
            out[itemA] = 1.f / (1.f + expf(-(pA + b3v)));
            out[itemB] = 1.f / (1.f + expf(-(pB + b3v)));
        }
        __syncwarp();   // protect rsm/h1s before next iteration overwrites
    }
}

// ---------------------------------------------------------------------------
extern "C" void kernel_launch(void* const* d_in, const int* in_sizes, int n_in,
                              void* d_out, int out_size) {
    const int*   concepts          = (const int*)d_in[0];
    const int*   interactions      = (const int*)d_in[1];
    const float* key_memory        = (const float*)d_in[2];
    const float* value_memory      = (const float*)d_in[3];
    const float* concept_embed     = (const float*)d_in[4];
    const float* interaction_embed = (const float*)d_in[5];
    const float* We = (const float*)d_in[6];
    const float* be = (const float*)d_in[7];
    const float* Wa = (const float*)d_in[8];
    const float* ba = (const float*)d_in[9];
    const float* W1 = (const float*)d_in[10];
    const float* b1 = (const float*)d_in[11];
    const float* W2 = (const float*)d_in[12];
    const float* b2 = (const float*)d_in[13];
    const float* W3 = (const float*)d_in[14];
    const float* b3 = (const float*)d_in[15];
    float* out = (float*)d_out;

    cudaFuncSetAttribute(k_main, cudaFuncAttributeMaxDynamicSharedMemorySize, SMEM_MAIN);
    cudaFuncSetAttribute(k_mlp, cudaFuncAttributeMaxDynamicSharedMemorySize, 26240 * 4);

    k_transpose<<<(N_ * DK_) / 256, 256>>>(key_memory);
    k_wtab<<<N_ + 1, 512>>>(concept_embed);
    k_eatab<<<(2 * N_ + 1 + IPB - 1) / IPB, 256>>>(interaction_embed, We, be, Wa, ba);
    k_qc<<<N_ + 1, 64>>>(concept_embed, W1, b1);
    k_main<<<B_ * SLICES_, 512, SMEM_MAIN>>>(concepts, interactions, value_memory);
    k_mlp<<<256, 256, 26240 * 4>>>(concepts, W1, W2, b2, W3, b3, out);
}

// round 15
// speedup vs baseline: 1.1140x; 1.1140x over previous
#include <cuda_runtime.h>
#include <math.h>

#define B_      256
#define T_      512
#define N_      512
#define DK_     64
#define DV_     256
#define S_      64
#define F_      64
#define SLICES_ 4
#define RPS_    128   // memory rows per slice
#define TAU     1e-8f // w threshold: dropped mass <= ~512*TAU per step

// -------- device scratch (static __device__ arrays; no allocations) --------
__device__ float  g_keyT[DK_ * N_];                  // key_memory transposed (DK, N)
__device__ float2 g_wlist[(N_ + 1) * SLICES_ * RPS_]; // compacted (w, row) per (c, slice)
__device__ int    g_wcnt[(N_ + 1) * SLICES_];         // active count per (c, slice)
__device__ float  g_etab[(2 * N_ + 1) * DV_];         // sigmoid(We v + be) per interaction id
__device__ float  g_atab[(2 * N_ + 1) * DV_];         // tanh(Wa v + ba)   per interaction id
__device__ float  g_qc[(N_ + 1) * S_];                // W1[:,DV:] @ q + b1 per concept id
__device__ float  g_rpart[134217728];                 // (B, T, SLICES, DV) partial reads

// ---------------------------------------------------------------------------
// Precompute 0: transpose key_memory (N, DK) -> (DK, N)
__global__ void k_transpose(const float* __restrict__ key) {
    int idx = blockIdx.x * blockDim.x + threadIdx.x;   // 0 .. N*DK-1
    int n = idx >> 6;
    int k = idx & 63;
    g_keyT[k * N_ + n] = key[idx];
}

// Precompute 1: softmax attention per concept, compacted to active (w, row)
// lists per slice with a deterministic ballot/scan (index-ascending order).
__global__ void k_wtab(const float* __restrict__ cemb) {
    int c = blockIdx.x;        // 0..512
    int n = threadIdx.x;       // 0..511
    __shared__ float q[DK_];
    __shared__ float red[512];
    __shared__ int wcnts[16];
    if (n < DK_) q[n] = cemb[c * DK_ + n];
    __syncthreads();
    float acc = 0.f;
#pragma unroll
    for (int k = 0; k < DK_; k++) acc = fmaf(q[k], g_keyT[k * N_ + n], acc);
    red[n] = acc; __syncthreads();
    for (int s = 256; s > 0; s >>= 1) { if (n < s) red[n] = fmaxf(red[n], red[n + s]); __syncthreads(); }
    float mx = red[0]; __syncthreads();
    float e = expf(acc - mx);
    red[n] = e; __syncthreads();
    for (int s = 256; s > 0; s >>= 1) { if (n < s) red[n] += red[n + s]; __syncthreads(); }
    float w = e / red[0];

    // deterministic compaction: each warp lies wholly inside one slice (128 = 4 warps)
    bool pred = (w >= TAU);
    unsigned mask = __ballot_sync(0xffffffffu, pred);
    int lane = n & 31, warp = n >> 5, slice = n >> 7, win = warp & 3;
    if (lane == 0) wcnts[warp] = __popc(mask);
    __syncthreads();
    int base = 0;
#pragma unroll
    for (int k = 0; k < 3; k++) if (k < win) base += wcnts[(slice << 2) + k];
    if (pred) {
        int pos = base + __popc(mask & ((1u << lane) - 1u));
        g_wlist[(c * SLICES_ + slice) * RPS_ + pos] = make_float2(w, __int_as_float(n & 127));
    }
    if ((n & 127) == 0)
        g_wcnt[c * SLICES_ + slice] = wcnts[slice * 4] + wcnts[slice * 4 + 1]
                                    + wcnts[slice * 4 + 2] + wcnts[slice * 4 + 3];
}

// Precompute 2: erase/add tables per interaction id (GEMV batched over 16 ids/block)
#define IPB 16
__global__ void k_eatab(const float* __restrict__ iemb,
                        const float* __restrict__ We, const float* __restrict__ be,
                        const float* __restrict__ Wa, const float* __restrict__ ba) {
    int i0 = blockIdx.x * IPB;
    int d = threadIdx.x;                 // 0..255 output dim
    __shared__ float v[IPB][DV_];
    for (int x = threadIdx.x; x < IPB * DV_; x += blockDim.x) {
        int ii = x >> 8, k = x & 255;
        int gi = i0 + ii;
        v[ii][k] = (gi <= 2 * N_) ? iemb[gi * DV_ + k] : 0.f;
    }
    __syncthreads();
    float aE[IPB], aA[IPB];
#pragma unroll
    for (int ii = 0; ii < IPB; ii++) { aE[ii] = 0.f; aA[ii] = 0.f; }
    for (int k = 0; k < DV_; k++) {
        float we = We[d * DV_ + k];
        float wa = Wa[d * DV_ + k];
#pragma unroll
        for (int ii = 0; ii < IPB; ii++) {
            aE[ii] = fmaf(we, v[ii][k], aE[ii]);
            aA[ii] = fmaf(wa, v[ii][k], aA[ii]);
        }
    }
    float beV = be[d], baV = ba[d];
#pragma unroll
    for (int ii = 0; ii < IPB; ii++) {
        int gi = i0 + ii;
        if (gi <= 2 * N_) {
            g_etab[gi * DV_ + d] = 1.f / (1.f + expf(-(aE[ii] + beV)));
            g_atab[gi * DV_ + d] = tanhf(aA[ii] + baV);
        }
    }
}

// Precompute 3: qc[c][s] = b1[s] + sum_k W1[s][DV+k] * q_c[k]
__global__ void k_qc(const float* __restrict__ cemb, const float* __restrict__ W1,
                     const float* __restrict__ b1) {
    int c = blockIdx.x;
    int s = threadIdx.x;     // 0..63
    __shared__ float q[DK_];
    if (s < DK_) q[s] = cemb[c * DK_ + s];
    __syncthreads();
    float acc = b1[s];
#pragma unroll
    for (int k = 0; k < DK_; k++) acc = fmaf(W1[s * (DV_ + DK_) + DV_ + k], q[k], acc);
    g_qc[c * S_ + s] = acc;
}

// ---------------------------------------------------------------------------
// Main recurrence (SPARSE, 2-step software pipeline, 1 barrier/step).
// One CTA per (batch, slice); slice state (128x256 fp32 = 128KB) in SMEM.
// Only rows with w >= TAU are touched. 512 threads: col = t&255, half = t>>8
// splits the active list by parity. Ping-pong register sets A/B carry
// (cnt, -e, a, list-entry) with a 2-step prefetch lead; the list is staged
// into SMEM one step before use. rex is double-buffered so the r-reduction
// runs after the single per-step barrier, overlapped with the next step.
#define SMEM_MAIN (131072 + 2048 + 4096 + 4096)
__global__ void __launch_bounds__(512, 1)
k_main(const int* __restrict__ concepts, const int* __restrict__ interactions,
       const float* __restrict__ vmem) {
    extern __shared__ char smraw[];
    float*  m_s   = (float*)smraw;                         // 32768 floats (128KB)
    float2* swl   = (float2*)(smraw + 131072);             // [2][128] (w, row)
    float*  rex   = (float*)(smraw + 131072 + 2048);       // [2][512] partials
    int*    c_seq = (int*)(smraw + 131072 + 2048 + 4096);  // 512
    int*    i_seq = c_seq + 512;                           // 512

    int batch = blockIdx.x >> 2;
    int slice = blockIdx.x & 3;
    int t = threadIdx.x;
    int col = t & 255, half = t >> 8;

    c_seq[t] = concepts[batch * T_ + t];
    i_seq[t] = interactions[batch * T_ + t];

    // load slice of value memory (contiguous rows) into SMEM
    {
        const float4* src = (const float4*)(vmem + (size_t)slice * RPS_ * DV_);
        float4* dst = (float4*)m_s;
#pragma unroll
        for (int i = 0; i < 16; i++) dst[t + i * 512] = src[t + i * 512];
    }
    __syncthreads();   // c_seq/i_seq visible

    // prologue: step 0 -> set A (list staged directly), step 1 -> set B (regs)
    int   cntA, cntB;
    float neA, aaA, neB, aaB;
    float2 plA = make_float2(0.f, 0.f), plB = make_float2(0.f, 0.f);
    {
        int c0 = c_seq[0], i0 = i_seq[0];
        int ls0 = c0 * SLICES_ + slice;
        cntA = g_wcnt[ls0];
        if (t < 128) swl[t] = g_wlist[ls0 * RPS_ + t];
        neA = -g_etab[i0 * DV_ + col];
        aaA =  g_atab[i0 * DV_ + col];

        int c1 = c_seq[1], i1 = i_seq[1];
        int ls1 = c1 * SLICES_ + slice;
        cntB = g_wcnt[ls1];
        if (t < 128) plB = g_wlist[ls1 * RPS_ + t];
        neB = -g_etab[i1 * DV_ + col];
        aaB =  g_atab[i1 * DV_ + col];
    }
    __syncthreads();   // swl[0] staged, m_s ready

    size_t obase = (size_t)batch * T_ * (SLICES_ * DV_) + (size_t)slice * DV_;

    // One step: consume set CUR; stage list for s+1 from set NXT; prefetch s+2
    // into set CUR; compute; barrier; reduce+store r for step s.
#define STEP_BODY(s, cntC, neC, aaC, plC, plN)                                   \
    {                                                                            \
        int   cntc = cntC;  float nec = neC, aac = aaC;                          \
        /* stage list for step s+1 (loaded 1 step ago; >=1 step of slack) */     \
        if (((s) + 1 < T_) && t < 128) swl[(((s) + 1) & 1) * 128 + t] = plN;     \
        /* prefetch step s+2 into set CUR (2-step lead) */                       \
        if ((s) + 2 < T_) {                                                      \
            int cn = c_seq[(s) + 2], in2 = i_seq[(s) + 2];                       \
            int ls = cn * SLICES_ + slice;                                       \
            cntC = g_wcnt[ls];                                                   \
            if (t < 128) plC = g_wlist[ls * RPS_ + t];                           \
            neC = -g_etab[in2 * DV_ + col];                                      \
            aaC =  g_atab[in2 * DV_ + col];                                      \
        }                                                                        \
        /* sparse read + erase-add update over active rows */                    \
        const float2* wl = swl + ((s) & 1) * 128;                                \
        float r = 0.f;                                                           \
        _Pragma("unroll 4")                                                      \
        for (int j = half; j < cntc; j += 2) {                                   \
            float2 e2 = wl[j];                                                   \
            float wv = e2.x;                                                     \
            int row = __float_as_int(e2.y);                                      \
            float* mp = m_s + (row << 8) + col;                                  \
            float mv = *mp;                                                      \
            r = fmaf(wv, mv, r);                                                 \
            float u = fmaf(nec, mv, aac);                                        \
            *mp = fmaf(wv, u, mv);                                               \
        }                                                                        \
        rex[((s) & 1) * 512 + t] = r;                                            \
        __syncthreads();                                                         \
        if (t < 256)                                                             \
            g_rpart[obase + (size_t)(s) * (SLICES_ * DV_) + t] =                 \
                rex[((s) & 1) * 512 + t] + rex[((s) & 1) * 512 + t + 256];       \
    }

    for (int step = 0; step < T_; step += 2) {
        STEP_BODY(step,     cntA, neA, aaA, plA, plB)
        STEP_BODY(step + 1, cntB, neB, aaB, plB, plA)
    }
#undef STEP_BODY
}

// ---------------------------------------------------------------------------
// Prediction head: reduce slice partials of r, then 320->64->64->1 MLP.
__global__ void k_mlp(const int* __restrict__ concepts,
                      const float* __restrict__ W1, const float* __restrict__ W2,
                      const float* __restrict__ b2, const float* __restrict__ W3,
                      const float* __restrict__ b3, float* __restrict__ out) {
    extern __shared__ float sm[];
    float* W1s = sm;                  // 64*260 = 16640
    float* W2s = W1s + 64 * 260;      // 64*68  = 4352
    float* W3s = W2s + 64 * 68;       // 64
    float* b2s = W3s + 64;            // 64
    float* rsm = b2s + 64;            // 16*256 = 4096
    float* h1s = rsm + 16 * 256;      // 16*64  = 1024   (total 26240 floats)
    int tid = threadIdx.x;
    for (int x = tid; x < 64 * 256; x += 256) {
        int s = x >> 8, d = x & 255;
        W1s[s * 260 + d] = W1[s * 320 + d];       // first DV columns of W1
    }
    for (int x = tid; x < 64 * 64; x += 256) {
        int s = x >> 6, k = x & 63;
        W2s[s * 68 + k] = W2[s * 64 + k];
    }
    if (tid < 64) { W3s[tid] = W3[tid]; b2s[tid] = b2[tid]; }
    __syncthreads();

    int w = tid >> 5, lane = tid & 31;
    float b3v = b3[0];
    float4* rA4 = (float4*)(rsm + (w * 2 + 0) * 256);
    float4* rB4 = (float4*)(rsm + (w * 2 + 1) * 256);
    float* h1A = h1s + (w * 2) * 64;
    float* h1B = h1A + 64;
    int pair0 = blockIdx.x * 8 + w;   // 2048 warp-slots, 65536 pairs, 32 iters

    for (int it = 0; it < 32; it++) {
        int pair = pair0 + it * 2048;
        int itemA = pair * 2, itemB = itemA + 1;
        const float4* rpA = (const float4*)(g_rpart + (size_t)itemA * (SLICES_ * DV_));
        const float4* rpB = (const float4*)(g_rpart + (size_t)itemB * (SLICES_ * DV_));
#pragma unroll
        for (int jj = 0; jj < 2; jj++) {
            int p = lane + 32 * jj;   // float4 index 0..63
            float4 a0 = rpA[p], a1 = rpA[64 + p], a2 = rpA[128 + p], a3 = rpA[192 + p];
            rA4[p] = make_float4(a0.x + a1.x + a2.x + a3.x, a0.y + a1.y + a2.y + a3.y,
                                 a0.z + a1.z + a2.z + a3.z, a0.w + a1.w + a2.w + a3.w);
            float4 c0 = rpB[p], c1 = rpB[64 + p], c2 = rpB[128 + p], c3 = rpB[192 + p];
            rB4[p] = make_float4(c0.x + c1.x + c2.x + c3.x, c0.y + c1.y + c2.y + c3.y,
                                 c0.z + c1.z + c2.z + c3.z, c0.w + c1.w + c2.w + c3.w);
        }
        __syncwarp();
        int cA = concepts[itemA];
        int cB = concepts[itemB];
        float acc00 = g_qc[cA * 64 + lane];
        float acc01 = g_qc[cA * 64 + lane + 32];
        float acc10 = g_qc[cB * 64 + lane];
        float acc11 = g_qc[cB * 64 + lane + 32];
#pragma unroll 8
        for (int d4 = 0; d4 < 64; d4++) {
            float4 ra = rA4[d4];
            float4 rb = rB4[d4];
            float4 w0 = *(const float4*)&W1s[lane * 260 + d4 * 4];
            float4 w1 = *(const float4*)&W1s[(lane + 32) * 260 + d4 * 4];
            acc00 += w0.x * ra.x + w0.y * ra.y + w0.z * ra.z + w0.w * ra.w;
            acc10 += w0.x * rb.x + w0.y * rb.y + w0.z * rb.z + w0.w * rb.w;
            acc01 += w1.x * ra.x + w1.y * ra.y + w1.z * ra.z + w1.w * ra.w;
            acc11 += w1.x * rb.x + w1.y * rb.y + w1.z * rb.z + w1.w * rb.w;
        }
        h1A[lane]      = fmaxf(acc00, 0.f);
        h1A[lane + 32] = fmaxf(acc01, 0.f);
        h1B[lane]      = fmaxf(acc10, 0.f);
        h1B[lane + 32] = fmaxf(acc11, 0.f);
        __syncwarp();
        float h2[2][2];
#pragma unroll
        for (int o = 0; o < 2; o++) {
            int s = lane + 32 * o;
            float aA = b2s[s], aB = aA;
#pragma unroll
            for (int k4 = 0; k4 < 16; k4++) {
                float4 wv = *(const float4*)&W2s[s * 68 + k4 * 4];
                float4 ha = *(const float4*)&h1A[k4 * 4];
                float4 hb = *(const float4*)&h1B[k4 * 4];
                aA += wv.x * ha.x + wv.y * ha.y + wv.z * ha.z + wv.w * ha.w;
                aB += wv.x * hb.x + wv.y * hb.y + wv.z * hb.z + wv.w * hb.w;
            }
            h2[0][o] = fmaxf(aA, 0.f);
            h2[1][o] = fmaxf(aB, 0.f);
        }
        float pA = W3s[lane] * h2[0][0] + W3s[lane + 32] * h2[0][1];
        float pB = W3s[lane] * h2[1][0] + W3s[lane + 32] * h2[1][1];
#pragma unroll
        for (int off = 16; off > 0; off >>= 1) {
            pA += __shfl_xor_sync(0xffffffffu, pA, off);
            pB += __shfl_xor_sync(0xffffffffu, pB, off);
        }
        if (lane == 0) {
            out[itemA] = 1.f / (1.f + expf(-(pA + b3v)));
            out[itemB] = 1.f / (1.f + expf(-(pB + b3v)));
        }
        __syncwarp();   // protect rsm/h1s before next iteration overwrites
    }
}

// ---------------------------------------------------------------------------
extern "C" void kernel_launch(void* const* d_in, const int* in_sizes, int n_in,
                              void* d_out, int out_size) {
    const int*   concepts          = (const int*)d_in[0];
    const int*   interactions      = (const int*)d_in[1];
    const float* key_memory        = (const float*)d_in[2];
    const float* value_memory      = (const float*)d_in[3];
    const float* concept_embed     = (const float*)d_in[4];
    const float* interaction_embed = (const float*)d_in[5];
    const float* We = (const float*)d_in[6];
    const float* be = (const float*)d_in[7];
    const float* Wa = (const float*)d_in[8];
    const float* ba = (const float*)d_in[9];
    const float* W1 = (const float*)d_in[10];
    const float* b1 = (const float*)d_in[11];
    const float* W2 = (const float*)d_in[12];
    const float* b2 = (const float*)d_in[13];
    const float* W3 = (const float*)d_in[14];
    const float* b3 = (const float*)d_in[15];
    float* out = (float*)d_out;

    cudaFuncSetAttribute(k_main, cudaFuncAttributeMaxDynamicSharedMemorySize, SMEM_MAIN);
    cudaFuncSetAttribute(k_mlp, cudaFuncAttributeMaxDynamicSharedMemorySize, 26240 * 4);

    k_transpose<<<(N_ * DK_) / 256, 256>>>(key_memory);
    k_wtab<<<N_ + 1, 512>>>(concept_embed);
    k_eatab<<<(2 * N_ + 1 + IPB - 1) / IPB, 256>>>(interaction_embed, We, be, Wa, ba);
    k_qc<<<N_ + 1, 64>>>(concept_embed, W1, b1);
    k_main<<<B_ * SLICES_, 512, SMEM_MAIN>>>(concepts, interactions, value_memory);
    k_mlp<<<256, 256, 26240 * 4>>>(concepts, W1, W2, b2, W3, b3, out);
}

// round 16
// speedup vs baseline: 1.1160x; 1.0018x over previous
#include <cuda_runtime.h>
#include <math.h>

#define B_      256
#define T_      512
#define N_      512
#define DK_     64
#define DV_     256
#define S_      64
#define F_      64
#define SLICES_ 4
#define RPS_    128   // memory rows per slice
#define TAU     1e-8f // w threshold: dropped mass <= ~512*TAU per step

// -------- device scratch (static __device__ arrays; no allocations) --------
__device__ float  g_keyT[DK_ * N_];                  // key_memory transposed (DK, N)
__device__ float2 g_wlist[(N_ + 1) * SLICES_ * RPS_]; // compacted (w, row) per (c, slice)
__device__ int    g_wcnt[(N_ + 1) * SLICES_];         // active count per (c, slice)
__device__ float  g_etab[(2 * N_ + 1) * DV_];         // sigmoid(We v + be) per interaction id
__device__ float  g_atab[(2 * N_ + 1) * DV_];         // tanh(Wa v + ba)   per interaction id
__device__ float  g_qc[(N_ + 1) * S_];                // W1[:,DV:] @ q + b1 per concept id
__device__ float  g_rpart[134217728];                 // (B, T, SLICES, DV) partial reads

// ---------------------------------------------------------------------------
// Precompute 0: transpose key_memory (N, DK) -> (DK, N)
__global__ void k_transpose(const float* __restrict__ key) {
    int idx = blockIdx.x * blockDim.x + threadIdx.x;   // 0 .. N*DK-1
    int n = idx >> 6;
    int k = idx & 63;
    g_keyT[k * N_ + n] = key[idx];
}

// Precompute 1: softmax attention per concept, compacted to active (w, row)
// lists per slice with a deterministic ballot/scan (index-ascending order).
__global__ void k_wtab(const float* __restrict__ cemb) {
    int c = blockIdx.x;        // 0..512
    int n = threadIdx.x;       // 0..511
    __shared__ float q[DK_];
    __shared__ float red[512];
    __shared__ int wcnts[16];
    if (n < DK_) q[n] = cemb[c * DK_ + n];
    __syncthreads();
    float acc = 0.f;
#pragma unroll
    for (int k = 0; k < DK_; k++) acc = fmaf(q[k], g_keyT[k * N_ + n], acc);
    red[n] = acc; __syncthreads();
    for (int s = 256; s > 0; s >>= 1) { if (n < s) red[n] = fmaxf(red[n], red[n + s]); __syncthreads(); }
    float mx = red[0]; __syncthreads();
    float e = expf(acc - mx);
    red[n] = e; __syncthreads();
    for (int s = 256; s > 0; s >>= 1) { if (n < s) red[n] += red[n + s]; __syncthreads(); }
    float w = e / red[0];

    // deterministic compaction: each warp lies wholly inside one slice (128 = 4 warps)
    bool pred = (w >= TAU);
    unsigned mask = __ballot_sync(0xffffffffu, pred);
    int lane = n & 31, warp = n >> 5, slice = n >> 7, win = warp & 3;
    if (lane == 0) wcnts[warp] = __popc(mask);
    __syncthreads();
    int base = 0;
#pragma unroll
    for (int k = 0; k < 3; k++) if (k < win) base += wcnts[(slice << 2) + k];
    if (pred) {
        int pos = base + __popc(mask & ((1u << lane) - 1u));
        g_wlist[(c * SLICES_ + slice) * RPS_ + pos] = make_float2(w, __int_as_float(n & 127));
    }
    if ((n & 127) == 0)
        g_wcnt[c * SLICES_ + slice] = wcnts[slice * 4] + wcnts[slice * 4 + 1]
                                    + wcnts[slice * 4 + 2] + wcnts[slice * 4 + 3];
}

// Precompute 2: erase/add tables per interaction id (GEMV batched over 16 ids/block)
#define IPB 16
__global__ void k_eatab(const float* __restrict__ iemb,
                        const float* __restrict__ We, const float* __restrict__ be,
                        const float* __restrict__ Wa, const float* __restrict__ ba) {
    int i0 = blockIdx.x * IPB;
    int d = threadIdx.x;                 // 0..255 output dim
    __shared__ float v[IPB][DV_];
    for (int x = threadIdx.x; x < IPB * DV_; x += blockDim.x) {
        int ii = x >> 8, k = x & 255;
        int gi = i0 + ii;
        v[ii][k] = (gi <= 2 * N_) ? iemb[gi * DV_ + k] : 0.f;
    }
    __syncthreads();
    float aE[IPB], aA[IPB];
#pragma unroll
    for (int ii = 0; ii < IPB; ii++) { aE[ii] = 0.f; aA[ii] = 0.f; }
    for (int k = 0; k < DV_; k++) {
        float we = We[d * DV_ + k];
        float wa = Wa[d * DV_ + k];
#pragma unroll
        for (int ii = 0; ii < IPB; ii++) {
            aE[ii] = fmaf(we, v[ii][k], aE[ii]);
            aA[ii] = fmaf(wa, v[ii][k], aA[ii]);
        }
    }
    float beV = be[d], baV = ba[d];
#pragma unroll
    for (int ii = 0; ii < IPB; ii++) {
        int gi = i0 + ii;
        if (gi <= 2 * N_) {
            g_etab[gi * DV_ + d] = 1.f / (1.f + expf(-(aE[ii] + beV)));
            g_atab[gi * DV_ + d] = tanhf(aA[ii] + baV);
        }
    }
}

// Precompute 3: qc[c][s] = b1[s] + sum_k W1[s][DV+k] * q_c[k]
__global__ void k_qc(const float* __restrict__ cemb, const float* __restrict__ W1,
                     const float* __restrict__ b1) {
    int c = blockIdx.x;
    int s = threadIdx.x;     // 0..63
    __shared__ float q[DK_];
    if (s < DK_) q[s] = cemb[c * DK_ + s];
    __syncthreads();
    float acc = b1[s];
#pragma unroll
    for (int k = 0; k < DK_; k++) acc = fmaf(W1[s * (DV_ + DK_) + DV_ + k], q[k], acc);
    g_qc[c * S_ + s] = acc;
}

// ---------------------------------------------------------------------------
// Main recurrence (SPARSE, 2-step software pipeline, 1 barrier/step).
// One CTA per (batch, slice); slice state (128x256 fp32 = 128KB) in SMEM.
// Only rows with w >= TAU are touched. 512 threads: col = t&255, half = t>>8
// splits the active list by parity. Ping-pong register sets A/B carry
// (cnt, -e, a, list-entry) with a 2-step prefetch lead; the list is staged
// into SMEM one step before use. rex is double-buffered so the r-reduction
// runs after the single per-step barrier, overlapped with the next step.
#define SMEM_MAIN (131072 + 2048 + 4096 + 4096)
__global__ void __launch_bounds__(512, 1)
k_main(const int* __restrict__ concepts, const int* __restrict__ interactions,
       const float* __restrict__ vmem) {
    extern __shared__ char smraw[];
    float*  m_s   = (float*)smraw;                         // 32768 floats (128KB)
    float2* swl   = (float2*)(smraw + 131072);             // [2][128] (w, row)
    float*  rex   = (float*)(smraw + 131072 + 2048);       // [2][512] partials
    int*    c_seq = (int*)(smraw + 131072 + 2048 + 4096);  // 512
    int*    i_seq = c_seq + 512;                           // 512

    int batch = blockIdx.x >> 2;
    int slice = blockIdx.x & 3;
    int t = threadIdx.x;
    int col = t & 255, half = t >> 8;

    c_seq[t] = concepts[batch * T_ + t];
    i_seq[t] = interactions[batch * T_ + t];

    // load slice of value memory (contiguous rows) into SMEM
    {
        const float4* src = (const float4*)(vmem + (size_t)slice * RPS_ * DV_);
        float4* dst = (float4*)m_s;
#pragma unroll
        for (int i = 0; i < 16; i++) dst[t + i * 512] = src[t + i * 512];
    }
    __syncthreads();   // c_seq/i_seq visible

    // prologue: step 0 -> set A (list staged directly), step 1 -> set B (regs)
    int   cntA, cntB;
    float neA, aaA, neB, aaB;
    float2 plA = make_float2(0.f, 0.f), plB = make_float2(0.f, 0.f);
    {
        int c0 = c_seq[0], i0 = i_seq[0];
        int ls0 = c0 * SLICES_ + slice;
        cntA = g_wcnt[ls0];
        if (t < 128) swl[t] = g_wlist[ls0 * RPS_ + t];
        neA = -g_etab[i0 * DV_ + col];
        aaA =  g_atab[i0 * DV_ + col];

        int c1 = c_seq[1], i1 = i_seq[1];
        int ls1 = c1 * SLICES_ + slice;
        cntB = g_wcnt[ls1];
        if (t < 128) plB = g_wlist[ls1 * RPS_ + t];
        neB = -g_etab[i1 * DV_ + col];
        aaB =  g_atab[i1 * DV_ + col];
    }
    __syncthreads();   // swl[0] staged, m_s ready

    size_t obase = (size_t)batch * T_ * (SLICES_ * DV_) + (size_t)slice * DV_;

    // One step: consume set CUR; stage list for s+1 from set NXT; prefetch s+2
    // into set CUR; compute; barrier; reduce+store r for step s.
#define STEP_BODY(s, cntC, neC, aaC, plC, plN)                                   \
    {                                                                            \
        int   cntc = cntC;  float nec = neC, aac = aaC;                          \
        /* stage list for step s+1 (loaded 1 step ago; >=1 step of slack) */     \
        if (((s) + 1 < T_) && t < 128) swl[(((s) + 1) & 1) * 128 + t] = plN;     \
        /* prefetch step s+2 into set CUR (2-step lead) */                       \
        if ((s) + 2 < T_) {                                                      \
            int cn = c_seq[(s) + 2], in2 = i_seq[(s) + 2];                       \
            int ls = cn * SLICES_ + slice;                                       \
            cntC = g_wcnt[ls];                                                   \
            if (t < 128) plC = g_wlist[ls * RPS_ + t];                           \
            neC = -g_etab[in2 * DV_ + col];                                      \
            aaC =  g_atab[in2 * DV_ + col];                                      \
        }                                                                        \
        /* sparse read + erase-add update over active rows */                    \
        const float2* wl = swl + ((s) & 1) * 128;                                \
        float r = 0.f;                                                           \
        _Pragma("unroll 4")                                                      \
        for (int j = half; j < cntc; j += 2) {                                   \
            float2 e2 = wl[j];                                                   \
            float wv = e2.x;                                                     \
            int row = __float_as_int(e2.y);                                      \
            float* mp = m_s + (row << 8) + col;                                  \
            float mv = *mp;                                                      \
            r = fmaf(wv, mv, r);                                                 \
            float u = fmaf(nec, mv, aac);                                        \
            *mp = fmaf(wv, u, mv);                                               \
        }                                                                        \
        rex[((s) & 1) * 512 + t] = r;                                            \
        __syncthreads();                                                         \
        if (t < 256)                                                             \
            g_rpart[obase + (size_t)(s) * (SLICES_ * DV_) + t] =                 \
                rex[((s) & 1) * 512 + t] + rex[((s) & 1) * 512 + t + 256];       \
    }

    for (int step = 0; step < T_; step += 2) {
        STEP_BODY(step,     cntA, neA, aaA, plA, plB)
        STEP_BODY(step + 1, cntB, neB, aaB, plB, plA)
    }
#undef STEP_BODY
}

// ---------------------------------------------------------------------------
// Prediction head: reduce slice partials of r, then 320->64->64->1 MLP.
__global__ void k_mlp(const int* __restrict__ concepts,
                      const float* __restrict__ W1, const float* __restrict__ W2,
                      const float* __restrict__ b2, const float* __restrict__ W3,
                      const float* __restrict__ b3, float* __restrict__ out) {
    extern __shared__ float sm[];
    float* W1s = sm;                  // 64*260 = 16640
    float* W2s = W1s + 64 * 260;      // 64*68  = 4352
    float* W3s = W2s + 64 * 68;       // 64
    float* b2s = W3s + 64;            // 64
    float* rsm = b2s + 64;            // 16*256 = 4096
    float* h1s = rsm + 16 * 256;      // 16*64  = 1024   (total 26240 floats)
    int tid = threadIdx.x;
    for (int x = tid; x < 64 * 256; x += 256) {
        int s = x >> 8, d = x & 255;
        W1s[s * 260 + d] = W1[s * 320 + d];       // first DV columns of W1
    }
    for (int x = tid; x < 64 * 64; x += 256) {
        int s = x >> 6, k = x & 63;
        W2s[s * 68 + k] = W2[s * 64 + k];
    }
    if (tid < 64) { W3s[tid] = W3[tid]; b2s[tid] = b2[tid]; }
    __syncthreads();

    int w = tid >> 5, lane = tid & 31;
    float b3v = b3[0];
    float4* rA4 = (float4*)(rsm + (w * 2 + 0) * 256);
    float4* rB4 = (float4*)(rsm + (w * 2 + 1) * 256);
    float* h1A = h1s + (w * 2) * 64;
    float* h1B = h1A + 64;
    int pair0 = blockIdx.x * 8 + w;   // 2048 warp-slots, 65536 pairs, 32 iters

    for (int it = 0; it < 32; it++) {
        int pair = pair0 + it * 2048;
        int itemA = pair * 2, itemB = itemA + 1;
        const float4* rpA = (const float4*)(g_rpart + (size_t)itemA * (SLICES_ * DV_));
        const float4* rpB = (const float4*)(g_rpart + (size_t)itemB * (SLICES_ * DV_));
#pragma unroll
        for (int jj = 0; jj < 2; jj++) {
            int p = lane + 32 * jj;   // float4 index 0..63
            float4 a0 = rpA[p], a1 = rpA[64 + p], a2 = rpA[128 + p], a3 = rpA[192 + p];
            rA4[p] = make_float4(a0.x + a1.x + a2.x + a3.x, a0.y + a1.y + a2.y + a3.y,
                                 a0.z + a1.z + a2.z + a3.z, a0.w + a1.w + a2.w + a3.w);
            float4 c0 = rpB[p], c1 = rpB[64 + p], c2 = rpB[128 + p], c3 = rpB[192 + p];
            rB4[p] = make_float4(c0.x + c1.x + c2.x + c3.x, c0.y + c1.y + c2.y + c3.y,
                                 c0.z + c1.z + c2.z + c3.z, c0.w + c1.w + c2.w + c3.w);
        }
        __syncwarp();
        int cA = concepts[itemA];
        int cB = concepts[itemB];
        float acc00 = g_qc[cA * 64 + lane];
        float acc01 = g_qc[cA * 64 + lane + 32];
        float acc10 = g_qc[cB * 64 + lane];
        float acc11 = g_qc[cB * 64 + lane + 32];
#pragma unroll 8
        for (int d4 = 0; d4 < 64; d4++) {
            float4 ra = rA4[d4];
            float4 rb = rB4[d4];
            float4 w0 = *(const float4*)&W1s[lane * 260 + d4 * 4];
            float4 w1 = *(const float4*)&W1s[(lane + 32) * 260 + d4 * 4];
            acc00 += w0.x * ra.x + w0.y * ra.y + w0.z * ra.z + w0.w * ra.w;
            acc10 += w0.x * rb.x + w0.y * rb.y + w0.z * rb.z + w0.w * rb.w;
            acc01 += w1.x * ra.x + w1.y * ra.y + w1.z * ra.z + w1.w * ra.w;
            acc11 += w1.x * rb.x + w1.y * rb.y + w1.z * rb.z + w1.w * rb.w;
        }
        h1A[lane]      = fmaxf(acc00, 0.f);
        h1A[lane + 32] = fmaxf(acc01, 0.f);
        h1B[lane]      = fmaxf(acc10, 0.f);
        h1B[lane + 32] = fmaxf(acc11, 0.f);
        __syncwarp();
        float h2[2][2];
#pragma unroll
        for (int o = 0; o < 2; o++) {
            int s = lane + 32 * o;
            float aA = b2s[s], aB = aA;
#pragma unroll
            for (int k4 = 0; k4 < 16; k4++) {
                float4 wv = *(const float4*)&W2s[s * 68 + k4 * 4];
                float4 ha = *(const float4*)&h1A[k4 * 4];
                float4 hb = *(const float4*)&h1B[k4 * 4];
                aA += wv.x * ha.x + wv.y * ha.y + wv.z * ha.z + wv.w * ha.w;
                aB += wv.x * hb.x + wv.y * hb.y + wv.z * hb.z + wv.w * hb.w;
            }
            h2[0][o] = fmaxf(aA, 0.f);
            h2[1][o] = fmaxf(aB, 0.f);
        }
        float pA = W3s[lane] * h2[0][0] + W3s[lane + 32] * h2[0][1];
        float pB = W3s[lane] * h2[1][0] + W3s[lane + 32] * h2[1][1];
#pragma unroll
        for (int off = 16; off > 0; off >>= 1) {
            pA += __shfl_xor_sync(0xffffffffu, pA, off);
            pB += __shfl_xor_sync(0xffffffffu, pB, off);
        }
        if (lane == 0) {
            out[itemA] = 1.f / (1.f + expf(-(pA + b3v)));
            out[itemB] = 1.f / (1.f + expf(-(pB + b3v)));
        }
        __syncwarp();   // protect rsm/h1s before next iteration overwrites
    }
}

// ---------------------------------------------------------------------------
extern "C" void kernel_launch(void* const* d_in, const int* in_sizes, int n_in,
                              void* d_out, int out_size) {
    const int*   concepts          = (const int*)d_in[0];
    const int*   interactions      = (const int*)d_in[1];
    const float* key_memory        = (const float*)d_in[2];
    const float* value_memory      = (const float*)d_in[3];
    const float* concept_embed     = (const float*)d_in[4];
    const float* interaction_embed = (const float*)d_in[5];
    const float* We = (const float*)d_in[6];
    const float* be = (const float*)d_in[7];
    const float* Wa = (const float*)d_in[8];
    const float* ba = (const float*)d_in[9];
    const float* W1 = (const float*)d_in[10];
    const float* b1 = (const float*)d_in[11];
    const float* W2 = (const float*)d_in[12];
    const float* b2 = (const float*)d_in[13];
    const float* W3 = (const float*)d_in[14];
    const float* b3 = (const float*)d_in[15];
    float* out = (float*)d_out;

    cudaFuncSetAttribute(k_main, cudaFuncAttributeMaxDynamicSharedMemorySize, SMEM_MAIN);
    cudaFuncSetAttribute(k_mlp, cudaFuncAttributeMaxDynamicSharedMemorySize, 26240 * 4);

    k_transpose<<<(N_ * DK_) / 256, 256>>>(key_memory);
    k_wtab<<<N_ + 1, 512>>>(concept_embed);
    k_eatab<<<(2 * N_ + 1 + IPB - 1) / IPB, 256>>>(interaction_embed, We, be, Wa, ba);
    k_qc<<<N_ + 1, 64>>>(concept_embed, W1, b1);
    k_main<<<B_ * SLICES_, 512, SMEM_MAIN>>>(concepts, interactions, value_memory);
    k_mlp<<<256, 256, 26240 * 4>>>(concepts, W1, W2, b2, W3, b3, out);
}

// round 17
// speedup vs baseline: 1.8882x; 1.6919x over previous
#include <cuda_runtime.h>
#include <math.h>

#define B_      256
#define T_      512
#define N_      512
#define DK_     64
#define DV_     256
#define S_      64
#define F_      64
#define SLICES_ 4
#define RPS_    128   // memory rows per slice
#define TAU     1e-6f // w threshold; measured dropped-mass impact ~100x below bound

// -------- device scratch (static __device__ arrays; no allocations) --------
__device__ float  g_keyT[DK_ * N_];                  // key_memory transposed (DK, N)
__device__ float2 g_wlist[(N_ + 1) * SLICES_ * RPS_]; // compacted (w, row) per (c, slice)
__device__ int    g_wcnt[(N_ + 1) * SLICES_];         // active count per (c, slice)
__device__ float  g_etab[(2 * N_ + 1) * DV_];         // sigmoid(We v + be) per interaction id
__device__ float  g_atab[(2 * N_ + 1) * DV_];         // tanh(Wa v + ba)   per interaction id
__device__ float  g_qc[(N_ + 1) * S_];                // W1[:,DV:] @ q + b1 per concept id
__device__ float  g_rpart[134217728];                 // (B, T, SLICES, DV) partial reads

// ---------------------------------------------------------------------------
// Precompute 0: transpose key_memory (N, DK) -> (DK, N)
__global__ void k_transpose(const float* __restrict__ key) {
    int idx = blockIdx.x * blockDim.x + threadIdx.x;   // 0 .. N*DK-1
    int n = idx >> 6;
    int k = idx & 63;
    g_keyT[k * N_ + n] = key[idx];
}

// Precompute 1: softmax attention per concept, compacted to active (w, row)
// lists per slice with a deterministic ballot/scan (index-ascending order).
__global__ void k_wtab(const float* __restrict__ cemb) {
    int c = blockIdx.x;        // 0..512
    int n = threadIdx.x;       // 0..511
    __shared__ float q[DK_];
    __shared__ float red[512];
    __shared__ int wcnts[16];
    if (n < DK_) q[n] = cemb[c * DK_ + n];
    __syncthreads();
    float acc = 0.f;
#pragma unroll
    for (int k = 0; k < DK_; k++) acc = fmaf(q[k], g_keyT[k * N_ + n], acc);
    red[n] = acc; __syncthreads();
    for (int s = 256; s > 0; s >>= 1) { if (n < s) red[n] = fmaxf(red[n], red[n + s]); __syncthreads(); }
    float mx = red[0]; __syncthreads();
    float e = expf(acc - mx);
    red[n] = e; __syncthreads();
    for (int s = 256; s > 0; s >>= 1) { if (n < s) red[n] += red[n + s]; __syncthreads(); }
    float w = e / red[0];

    // deterministic compaction: each warp lies wholly inside one slice (128 = 4 warps)
    bool pred = (w >= TAU);
    unsigned mask = __ballot_sync(0xffffffffu, pred);
    int lane = n & 31, warp = n >> 5, slice = n >> 7, win = warp & 3;
    if (lane == 0) wcnts[warp] = __popc(mask);
    __syncthreads();
    int base = 0;
#pragma unroll
    for (int k = 0; k < 3; k++) if (k < win) base += wcnts[(slice << 2) + k];
    if (pred) {
        int pos = base + __popc(mask & ((1u << lane) - 1u));
        g_wlist[(c * SLICES_ + slice) * RPS_ + pos] = make_float2(w, __int_as_float(n & 127));
    }
    if ((n & 127) == 0)
        g_wcnt[c * SLICES_ + slice] = wcnts[slice * 4] + wcnts[slice * 4 + 1]
                                    + wcnts[slice * 4 + 2] + wcnts[slice * 4 + 3];
}

// Precompute 2: erase/add tables per interaction id (GEMV batched over 16 ids/block)
#define IPB 16
__global__ void k_eatab(const float* __restrict__ iemb,
                        const float* __restrict__ We, const float* __restrict__ be,
                        const float* __restrict__ Wa, const float* __restrict__ ba) {
    int i0 = blockIdx.x * IPB;
    int d = threadIdx.x;                 // 0..255 output dim
    __shared__ float v[IPB][DV_];
    for (int x = threadIdx.x; x < IPB * DV_; x += blockDim.x) {
        int ii = x >> 8, k = x & 255;
        int gi = i0 + ii;
        v[ii][k] = (gi <= 2 * N_) ? iemb[gi * DV_ + k] : 0.f;
    }
    __syncthreads();
    float aE[IPB], aA[IPB];
#pragma unroll
    for (int ii = 0; ii < IPB; ii++) { aE[ii] = 0.f; aA[ii] = 0.f; }
    for (int k = 0; k < DV_; k++) {
        float we = We[d * DV_ + k];
        float wa = Wa[d * DV_ + k];
#pragma unroll
        for (int ii = 0; ii < IPB; ii++) {
            aE[ii] = fmaf(we, v[ii][k], aE[ii]);
            aA[ii] = fmaf(wa, v[ii][k], aA[ii]);
        }
    }
    float beV = be[d], baV = ba[d];
#pragma unroll
    for (int ii = 0; ii < IPB; ii++) {
        int gi = i0 + ii;
        if (gi <= 2 * N_) {
            g_etab[gi * DV_ + d] = 1.f / (1.f + expf(-(aE[ii] + beV)));
            g_atab[gi * DV_ + d] = tanhf(aA[ii] + baV);
        }
    }
}

// Precompute 3: qc[c][s] = b1[s] + sum_k W1[s][DV+k] * q_c[k]
__global__ void k_qc(const float* __restrict__ cemb, const float* __restrict__ W1,
                     const float* __restrict__ b1) {
    int c = blockIdx.x;
    int s = threadIdx.x;     // 0..63
    __shared__ float q[DK_];
    if (s < DK_) q[s] = cemb[c * DK_ + s];
    __syncthreads();
    float acc = b1[s];
#pragma unroll
    for (int k = 0; k < DK_; k++) acc = fmaf(W1[s * (DV_ + DK_) + DV_ + k], q[k], acc);
    g_qc[c * S_ + s] = acc;
}

// ---------------------------------------------------------------------------
// Main recurrence (SPARSE, 4-step prefetch ring, 1 barrier/step).
// One CTA per (batch, slice); slice state (128x256 fp32 = 128KB) in SMEM.
// Only rows with w >= TAU are touched (~13/slice at TAU=1e-6).
// 512 threads: col-pair p = t&127 (cols 2p,2p+1), quarter q = t>>7 walks the
// active list with stride 4. Tables for step s+4 are prefetched at step s
// (~3-4 steps of latency slack); the (w,row) list is staged into SMEM one
// step before use. rex is double-buffered so the r-reduction runs after the
// single per-step barrier, overlapped with the next step's compute.
// g_rpart is written with __stcs (evict-first) so the 512MB stream does not
// evict the hot tables from L2.
#define SMEM_MAIN (131072 + 2048 + 8192 + 4096)
__global__ void __launch_bounds__(512, 1)
k_main(const int* __restrict__ concepts, const int* __restrict__ interactions,
       const float* __restrict__ vmem) {
    extern __shared__ char smraw[];
    float*  m_s   = (float*)smraw;                          // 32768 floats (128KB)
    float2* swl   = (float2*)(smraw + 131072);              // [2][128] (w, row)
    float2* rex   = (float2*)(smraw + 131072 + 2048);       // [2][4][128] partials
    int*    c_seq = (int*)(smraw + 131072 + 2048 + 8192);   // 512
    int*    i_seq = c_seq + 512;                            // 512

    int batch = blockIdx.x >> 2;
    int slice = blockIdx.x & 3;
    int t = threadIdx.x;
    int p = t & 127, q = t >> 7;          // col-pair, quarter
    float* m_col = m_s + 2 * p;

    c_seq[t] = concepts[batch * T_ + t];
    i_seq[t] = interactions[batch * T_ + t];

    // load slice of value memory (contiguous rows) into SMEM
    {
        const float4* src = (const float4*)(vmem + (size_t)slice * RPS_ * DV_);
        float4* dst = (float4*)m_s;
#pragma unroll
        for (int i = 0; i < 16; i++) dst[t + i * 512] = src[t + i * 512];
    }
    __syncthreads();   // c_seq/i_seq visible

    // prologue: load sets for steps 0..3; step 0's list goes straight to swl[0]
    int    cnt0, cnt1, cnt2, cnt3;
    float2 ne0, ne1, ne2, ne3, aa0, aa1, aa2, aa3;
    float2 pl0, pl1, pl2, pl3;
    pl0 = pl1 = pl2 = pl3 = make_float2(0.f, 0.f);
#define PRO_LOAD(s, cntS, neS, aaS, plS)                                        \
    {                                                                           \
        int c = c_seq[s], i = i_seq[s];                                         \
        int ls = c * SLICES_ + slice;                                           \
        cntS = g_wcnt[ls];                                                      \
        if (t < 128) plS = g_wlist[ls * RPS_ + t];                              \
        float2 ev = *(const float2*)(g_etab + (size_t)i * DV_ + 2 * p);         \
        neS = make_float2(-ev.x, -ev.y);                                        \
        aaS = *(const float2*)(g_atab + (size_t)i * DV_ + 2 * p);               \
    }
    PRO_LOAD(0, cnt0, ne0, aa0, pl0)
    if (t < 128) swl[t] = pl0;
    PRO_LOAD(1, cnt1, ne1, aa1, pl1)
    PRO_LOAD(2, cnt2, ne2, aa2, pl2)
    PRO_LOAD(3, cnt3, ne3, aa3, pl3)
#undef PRO_LOAD
    __syncthreads();   // swl[0] staged, m_s ready

    size_t obase = (size_t)batch * T_ * (SLICES_ * DV_) + (size_t)slice * DV_;

    // One step: consume set CUR (local copy); stage list for s+1 from set NXT
    // (loaded 3 steps ago); prefetch s+4 into set CUR; compute; barrier;
    // reduce+store r for step s with evict-first stores.
#define STEP_BODY(s, cntC, neC, aaC, plC, plN)                                   \
    {                                                                            \
        int   cntc = cntC;  float2 nec = neC, aac = aaC;                         \
        if (((s) + 1 < T_) && t < 128) swl[(((s) + 1) & 1) * 128 + t] = plN;     \
        if ((s) + 4 < T_) {                                                      \
            int cn = c_seq[(s) + 4], in2 = i_seq[(s) + 4];                       \
            int ls = cn * SLICES_ + slice;                                       \
            cntC = g_wcnt[ls];                                                   \
            if (t < 128) plC = g_wlist[ls * RPS_ + t];                           \
            float2 ev = *(const float2*)(g_etab + (size_t)in2 * DV_ + 2 * p);    \
            neC = make_float2(-ev.x, -ev.y);                                     \
            aaC = *(const float2*)(g_atab + (size_t)in2 * DV_ + 2 * p);          \
        }                                                                        \
        const float2* wl = swl + ((s) & 1) * 128;                                \
        float rx = 0.f, ry = 0.f;                                                \
        _Pragma("unroll 2")                                                      \
        for (int j = q; j < cntc; j += 4) {                                      \
            float2 e2 = wl[j];                                                   \
            float wv = e2.x;                                                     \
            int row = __float_as_int(e2.y);                                      \
            float2* mp = (float2*)(m_col + (row << 8));                          \
            float2 mv = *mp;                                                     \
            rx = fmaf(wv, mv.x, rx);                                             \
            ry = fmaf(wv, mv.y, ry);                                             \
            float ux = fmaf(nec.x, mv.x, aac.x);                                 \
            float uy = fmaf(nec.y, mv.y, aac.y);                                 \
            mv.x = fmaf(wv, ux, mv.x);                                           \
            mv.y = fmaf(wv, uy, mv.y);                                           \
            *mp = mv;                                                            \
        }                                                                        \
        rex[((s) & 1) * 512 + q * 128 + p] = make_float2(rx, ry);                \
        __syncthreads();                                                         \
        if (t < 128) {                                                           \
            const float2* rb = rex + ((s) & 1) * 512;                            \
            float2 v0 = rb[t], v1 = rb[128 + t], v2 = rb[256 + t], v3 = rb[384 + t]; \
            float2 sv = make_float2(v0.x + v1.x + v2.x + v3.x,                   \
                                    v0.y + v1.y + v2.y + v3.y);                  \
            __stcs((float2*)(g_rpart + obase + (size_t)(s) * (SLICES_ * DV_) + 2 * t), sv); \
        }                                                                        \
    }

    for (int step = 0; step < T_; step += 4) {
        STEP_BODY(step,     cnt0, ne0, aa0, pl0, pl1)
        STEP_BODY(step + 1, cnt1, ne1, aa1, pl1, pl2)
        STEP_BODY(step + 2, cnt2, ne2, aa2, pl2, pl3)
        STEP_BODY(step + 3, cnt3, ne3, aa3, pl3, pl0)
    }
#undef STEP_BODY
}

// ---------------------------------------------------------------------------
// Prediction head: reduce slice partials of r, then 320->64->64->1 MLP.
__global__ void k_mlp(const int* __restrict__ concepts,
                      const float* __restrict__ W1, const float* __restrict__ W2,
                      const float* __restrict__ b2, const float* __restrict__ W3,
                      const float* __restrict__ b3, float* __restrict__ out) {
    extern __shared__ float sm[];
    float* W1s = sm;                  // 64*260 = 16640
    float* W2s = W1s + 64 * 260;      // 64*68  = 4352
    float* W3s = W2s + 64 * 68;       // 64
    float* b2s = W3s + 64;            // 64
    float* rsm = b2s + 64;            // 16*256 = 4096
    float* h1s = rsm + 16 * 256;      // 16*64  = 1024   (total 26240 floats)
    int tid = threadIdx.x;
    for (int x = tid; x < 64 * 256; x += 256) {
        int s = x >> 8, d = x & 255;
        W1s[s * 260 + d] = W1[s * 320 + d];       // first DV columns of W1
    }
    for (int x = tid; x < 64 * 64; x += 256) {
        int s = x >> 6, k = x & 63;
        W2s[s * 68 + k] = W2[s * 64 + k];
    }
    if (tid < 64) { W3s[tid] = W3[tid]; b2s[tid] = b2[tid]; }
    __syncthreads();

    int w = tid >> 5, lane = tid & 31;
    float b3v = b3[0];
    float4* rA4 = (float4*)(rsm + (w * 2 + 0) * 256);
    float4* rB4 = (float4*)(rsm + (w * 2 + 1) * 256);
    float* h1A = h1s + (w * 2) * 64;
    float* h1B = h1A + 64;
    int pair0 = blockIdx.x * 8 + w;   // 2048 warp-slots, 65536 pairs, 32 iters

    for (int it = 0; it < 32; it++) {
        int pair = pair0 + it * 2048;
        int itemA = pair * 2, itemB = itemA + 1;
        const float4* rpA = (const float4*)(g_rpart + (size_t)itemA * (SLICES_ * DV_));
        const float4* rpB = (const float4*)(g_rpart + (size_t)itemB * (SLICES_ * DV_));
#pragma unroll
        for (int jj = 0; jj < 2; jj++) {
            int pq = lane + 32 * jj;  // float4 index 0..63
            float4 a0 = __ldcs(rpA + pq),       a1 = __ldcs(rpA + 64 + pq);
            float4 a2 = __ldcs(rpA + 128 + pq), a3 = __ldcs(rpA + 192 + pq);
            rA4[pq] = make_float4(a0.x + a1.x + a2.x + a3.x, a0.y + a1.y + a2.y + a3.y,
                                  a0.z + a1.z + a2.z + a3.z, a0.w + a1.w + a2.w + a3.w);
            float4 c0 = __ldcs(rpB + pq),       c1 = __ldcs(rpB + 64 + pq);
            float4 c2 = __ldcs(rpB + 128 + pq), c3 = __ldcs(rpB + 192 + pq);
            rB4[pq] = make_float4(c0.x + c1.x + c2.x + c3.x, c0.y + c1.y + c2.y + c3.y,
                                  c0.z + c1.z + c2.z + c3.z, c0.w + c1.w + c2.w + c3.w);
        }
        __syncwarp();
        int cA = concepts[itemA];
        int cB = concepts[itemB];
        float acc00 = g_qc[cA * 64 + lane];
        float acc01 = g_qc[cA * 64 + lane + 32];
        float acc10 = g_qc[cB * 64 + lane];
        float acc11 = g_qc[cB * 64 + lane + 32];
#pragma unroll 8
        for (int d4 = 0; d4 < 64; d4++) {
            float4 ra = rA4[d4];
            float4 rb = rB4[d4];
            float4 w0 = *(const float4*)&W1s[lane * 260 + d4 * 4];
            float4 w1 = *(const float4*)&W1s[(lane + 32) * 260 + d4 * 4];
            acc00 += w0.x * ra.x + w0.y * ra.y + w0.z * ra.z + w0.w * ra.w;
            acc10 += w0.x * rb.x + w0.y * rb.y + w0.z * rb.z + w0.w * rb.w;
            acc01 += w1.x * ra.x + w1.y * ra.y + w1.z * ra.z + w1.w * ra.w;
            acc11 += w1.x * rb.x + w1.y * rb.y + w1.z * rb.z + w1.w * rb.w;
        }
        h1A[lane]      = fmaxf(acc00, 0.f);
        h1A[lane + 32] = fmaxf(acc01, 0.f);
        h1B[lane]      = fmaxf(acc10, 0.f);
        h1B[lane + 32] = fmaxf(acc11, 0.f);
        __syncwarp();
        float h2[2][2];
#pragma unroll
        for (int o = 0; o < 2; o++) {
            int s = lane + 32 * o;
            float aA = b2s[s], aB = aA;
#pragma unroll
            for (int k4 = 0; k4 < 16; k4++) {
                float4 wv = *(const float4*)&W2s[s * 68 + k4 * 4];
                float4 ha = *(const float4*)&h1A[k4 * 4];
                float4 hb = *(const float4*)&h1B[k4 * 4];
                aA += wv.x * ha.x + wv.y * ha.y + wv.z * ha.z + wv.w * ha.w;
                aB += wv.x * hb.x + wv.y * hb.y + wv.z * hb.z + wv.w * hb.w;
            }
            h2[0][o] = fmaxf(aA, 0.f);
            h2[1][o] = fmaxf(aB, 0.f);
        }
        float pA = W3s[lane] * h2[0][0] + W3s[lane + 32] * h2[0][1];
        float pB = W3s[lane] * h2[1][0] + W3s[lane + 32] * h2[1][1];
#pragma unroll
        for (int off = 16; off > 0; off >>= 1) {
            pA += __shfl_xor_sync(0xffffffffu, pA, off);
            pB += __shfl_xor_sync(0xffffffffu, pB, off);
        }
        if (lane == 0) {
            out[itemA] = 1.f / (1.f + expf(-(pA + b3v)));
            out[itemB] = 1.f / (1.f + expf(-(pB + b3v)));
        }
        __syncwarp();   // protect rsm/h1s before next iteration overwrites
    }
}

// ---------------------------------------------------------------------------
extern "C" void kernel_launch(void* const* d_in, const int* in_sizes, int n_in,
                              void* d_out, int out_size) {
    const int*   concepts          = (const int*)d_in[0];
    const int*   interactions      = (const int*)d_in[1];
    const float* key_memory        = (const float*)d_in[2];
    const float* value_memory      = (const float*)d_in[3];
    const float* concept_embed     = (const float*)d_in[4];
    const float* interaction_embed = (const float*)d_in[5];
    const float* We = (const float*)d_in[6];
    const float* be = (const float*)d_in[7];
    const float* Wa = (const float*)d_in[8];
    const float* ba = (const float*)d_in[9];
    const float* W1 = (const float*)d_in[10];
    const float* b1 = (const float*)d_in[11];
    const float* W2 = (const float*)d_in[12];
    const float* b2 = (const float*)d_in[13];
    const float* W3 = (const float*)d_in[14];
    const float* b3 = (const float*)d_in[15];
    float* out = (float*)d_out;

    cudaFuncSetAttribute(k_main, cudaFuncAttributeMaxDynamicSharedMemorySize, SMEM_MAIN);
    cudaFuncSetAttribute(k_mlp, cudaFuncAttributeMaxDynamicSharedMemorySize, 26240 * 4);

    k_transpose<<<(N_ * DK_) / 256, 256>>>(key_memory);
    k_wtab<<<N_ + 1, 512>>>(concept_embed);
    k_eatab<<<(2 * N_ + 1 + IPB - 1) / IPB, 256>>>(interaction_embed, We, be, Wa, ba);
    k_qc<<<N_ + 1, 64>>>(concept_embed, W1, b1);
    k_main<<<B_ * SLICES_, 512, SMEM_MAIN>>>(concepts, interactions, value_memory);
    k_mlp<<<256, 256, 26240 * 4>>>(concepts, W1, W2, b2, W3, b3, out);
}